// round 4
// baseline (speedup 1.0000x reference)
#include <cuda_runtime.h>

// Fused hyper-connection:
//   out[b,t,m,c] = sum_n x[b,t,n,c] * ( res_w[m,n] + softmax(post)[m]*softmax(pre)[n] )
// Precompute the combined 4x4 matrix W once, then stream 256MB -> 256MB.

__device__ float g_W[16];

__global__ void compute_w_kernel(const float* __restrict__ pre,
                                 const float* __restrict__ post,
                                 const float* __restrict__ res) {
    if (threadIdx.x != 0) return;
    float pw[4], qw[4];
    float m1 = -1e30f, m2 = -1e30f;
    #pragma unroll
    for (int i = 0; i < 4; i++) {
        m1 = fmaxf(m1, pre[i]);
        m2 = fmaxf(m2, post[i]);
    }
    float s1 = 0.f, s2 = 0.f;
    #pragma unroll
    for (int i = 0; i < 4; i++) {
        pw[i] = expf(pre[i] - m1); s1 += pw[i];
        qw[i] = expf(post[i] - m2); s2 += qw[i];
    }
    float r1 = 1.f / s1, r2 = 1.f / s2;
    #pragma unroll
    for (int i = 0; i < 4; i++) { pw[i] *= r1; qw[i] *= r2; }
    #pragma unroll
    for (int m = 0; m < 4; m++)
        #pragma unroll
        for (int n = 0; n < 4; n++)
            g_W[m * 4 + n] = res[m * 4 + n] + qw[m] * pw[n];
}

// Layout: x is (B,T,n,C) fp32 with B*T = 16384 "rows", each row = 4 slices of
// 1024 floats (= 256 float4). One thread handles one (row, c4): loads the
// 4 n-slices (4KB stride, coalesced within warp), applies W, stores 4 float4.
__global__ __launch_bounds__(256)
void hc_main_kernel(const float4* __restrict__ x, float4* __restrict__ out) {
    const unsigned idx = blockIdx.x * 256u + threadIdx.x;
    const unsigned row = idx >> 8;        // 0 .. 16383
    const unsigned c4  = idx & 255u;      // 0 .. 255

    const size_t base = (size_t)row * 1024 + c4;  // in float4 units

    float4 xn[4];
    #pragma unroll
    for (int n = 0; n < 4; n++)
        xn[n] = x[base + (size_t)n * 256];

    float W[16];
    #pragma unroll
    for (int i = 0; i < 16; i++)
        W[i] = g_W[i];

    #pragma unroll
    for (int m = 0; m < 4; m++) {
        float4 o;
        o.x = W[m*4+0]*xn[0].x + W[m*4+1]*xn[1].x + W[m*4+2]*xn[2].x + W[m*4+3]*xn[3].x;
        o.y = W[m*4+0]*xn[0].y + W[m*4+1]*xn[1].y + W[m*4+2]*xn[2].y + W[m*4+3]*xn[3].y;
        o.z = W[m*4+0]*xn[0].z + W[m*4+1]*xn[1].z + W[m*4+2]*xn[2].z + W[m*4+3]*xn[3].z;
        o.w = W[m*4+0]*xn[0].w + W[m*4+1]*xn[1].w + W[m*4+2]*xn[2].w + W[m*4+3]*xn[3].w;
        out[base + (size_t)m * 256] = o;
    }
}

extern "C" void kernel_launch(void* const* d_in, const int* in_sizes, int n_in,
                              void* d_out, int out_size) {
    const float* x    = (const float*)d_in[0];
    const float* pre  = (const float*)d_in[1];
    const float* post = (const float*)d_in[2];
    const float* res  = (const float*)d_in[3];
    float* out = (float*)d_out;

    compute_w_kernel<<<1, 32>>>(pre, post, res);

    // B*T = 16384 rows, 256 float4 per row per n-slice
    const unsigned total_threads = 16384u * 256u;
    hc_main_kernel<<<total_threads / 256u, 256u>>>((const float4*)x, (float4*)out);
}

// round 5
// speedup vs baseline: 1.0229x; 1.0229x over previous
#include <cuda_runtime.h>

// Fused hyper-connection:
//   out[b,t,m,c] = sum_n x[b,t,n,c] * ( res_w[m,n] + softmax(post)[m]*softmax(pre)[n] )
// W = res_w + post_sm (outer) pre_sm is computed per-block into smem (cheap,
// uniform loads broadcast from L2), then the kernel streams 256MB -> 256MB.

__global__ __launch_bounds__(256)
void hc_fused_kernel(const float4* __restrict__ x, float4* __restrict__ out,
                     const float* __restrict__ pre,
                     const float* __restrict__ post,
                     const float* __restrict__ res) {
    __shared__ float sW[16];
    if (threadIdx.x == 0) {
        float pw[4], qw[4];
        float m1 = -1e30f, m2 = -1e30f;
        #pragma unroll
        for (int i = 0; i < 4; i++) {
            m1 = fmaxf(m1, pre[i]);
            m2 = fmaxf(m2, post[i]);
        }
        float s1 = 0.f, s2 = 0.f;
        #pragma unroll
        for (int i = 0; i < 4; i++) {
            pw[i] = __expf(pre[i] - m1);  s1 += pw[i];
            qw[i] = __expf(post[i] - m2); s2 += qw[i];
        }
        const float r1 = 1.f / s1, r2 = 1.f / s2;
        #pragma unroll
        for (int m = 0; m < 4; m++)
            #pragma unroll
            for (int n = 0; n < 4; n++)
                sW[m * 4 + n] = res[m * 4 + n] + (qw[m] * r2) * (pw[n] * r1);
    }
    __syncthreads();

    const unsigned idx = blockIdx.x * 256u + threadIdx.x;
    const unsigned row = idx >> 8;        // 0 .. 16383  (B*T rows)
    const unsigned c4  = idx & 255u;      // 0 .. 255    (float4 within C=1024)

    const size_t base = (size_t)row * 1024 + c4;  // in float4 units

    float4 xn[4];
    #pragma unroll
    for (int n = 0; n < 4; n++)
        xn[n] = __ldcs(&x[base + (size_t)n * 256]);   // streaming, no reuse

    float W[16];
    #pragma unroll
    for (int i = 0; i < 16; i++)
        W[i] = sW[i];

    #pragma unroll
    for (int m = 0; m < 4; m++) {
        float4 o;
        o.x = W[m*4+0]*xn[0].x + W[m*4+1]*xn[1].x + W[m*4+2]*xn[2].x + W[m*4+3]*xn[3].x;
        o.y = W[m*4+0]*xn[0].y + W[m*4+1]*xn[1].y + W[m*4+2]*xn[2].y + W[m*4+3]*xn[3].y;
        o.z = W[m*4+0]*xn[0].z + W[m*4+1]*xn[1].z + W[m*4+2]*xn[2].z + W[m*4+3]*xn[3].z;
        o.w = W[m*4+0]*xn[0].w + W[m*4+1]*xn[1].w + W[m*4+2]*xn[2].w + W[m*4+3]*xn[3].w;
        __stcs(&out[base + (size_t)m * 256], o);      // streaming store
    }
}

extern "C" void kernel_launch(void* const* d_in, const int* in_sizes, int n_in,
                              void* d_out, int out_size) {
    const float* x    = (const float*)d_in[0];
    const float* pre  = (const float*)d_in[1];
    const float* post = (const float*)d_in[2];
    const float* res  = (const float*)d_in[3];
    float* out = (float*)d_out;

    // B*T = 16384 rows, 256 float4 per row per n-slice -> 4.19M threads
    const unsigned total_threads = 16384u * 256u;
    hc_fused_kernel<<<total_threads / 256u, 256u>>>(
        (const float4*)x, (float4*)out, pre, post, res);
}

// round 6
// speedup vs baseline: 1.0264x; 1.0035x over previous
#include <cuda_runtime.h>

// Fused hyper-connection:
//   out[b,t,m,c] = sum_n x[b,t,n,c] * ( res_w[m,n] + softmax(post)[m]*softmax(pre)[n] )
// W = res_w + post_sm (outer) pre_sm computed per-block into smem, then the
// kernel streams 256MB -> 256MB. Each thread processes TWO float4 columns
// (stride 128 float4 apart so every load instruction stays lane-contiguous)
// => 8 front-batched loads per thread (MLP_p1=8) for deeper latency hiding.

__global__ __launch_bounds__(256)
void hc_fused_kernel(const float4* __restrict__ x, float4* __restrict__ out,
                     const float* __restrict__ pre,
                     const float* __restrict__ post,
                     const float* __restrict__ res) {
    __shared__ float sW[16];
    if (threadIdx.x == 0) {
        float pw[4], qw[4];
        float m1 = -1e30f, m2 = -1e30f;
        #pragma unroll
        for (int i = 0; i < 4; i++) {
            m1 = fmaxf(m1, pre[i]);
            m2 = fmaxf(m2, post[i]);
        }
        float s1 = 0.f, s2 = 0.f;
        #pragma unroll
        for (int i = 0; i < 4; i++) {
            pw[i] = __expf(pre[i] - m1);  s1 += pw[i];
            qw[i] = __expf(post[i] - m2); s2 += qw[i];
        }
        const float r1 = 1.f / s1, r2 = 1.f / s2;
        #pragma unroll
        for (int m = 0; m < 4; m++)
            #pragma unroll
            for (int n = 0; n < 4; n++)
                sW[m * 4 + n] = res[m * 4 + n] + (qw[m] * r2) * (pw[n] * r1);
    }
    __syncthreads();

    const unsigned idx = blockIdx.x * 256u + threadIdx.x;
    const unsigned row = idx >> 7;        // 0 .. 16383  (B*T rows)
    const unsigned c4  = idx & 127u;      // 0 .. 127    (first of 2 float4 cols)

    const size_t base = (size_t)row * 1024 + c4;  // float4 units

    // 8 front-batched loads: n-slice stride 256, column stride 128
    float4 xn[4][2];
    #pragma unroll
    for (int n = 0; n < 4; n++)
        #pragma unroll
        for (int j = 0; j < 2; j++)
            xn[n][j] = __ldcs(&x[base + (size_t)n * 256 + (size_t)j * 128]);

    float W[16];
    #pragma unroll
    for (int i = 0; i < 16; i++)
        W[i] = sW[i];

    #pragma unroll
    for (int m = 0; m < 4; m++) {
        #pragma unroll
        for (int j = 0; j < 2; j++) {
            float4 o;
            o.x = W[m*4+0]*xn[0][j].x + W[m*4+1]*xn[1][j].x + W[m*4+2]*xn[2][j].x + W[m*4+3]*xn[3][j].x;
            o.y = W[m*4+0]*xn[0][j].y + W[m*4+1]*xn[1][j].y + W[m*4+2]*xn[2][j].y + W[m*4+3]*xn[3][j].y;
            o.z = W[m*4+0]*xn[0][j].z + W[m*4+1]*xn[1][j].z + W[m*4+2]*xn[2][j].z + W[m*4+3]*xn[3][j].z;
            o.w = W[m*4+0]*xn[0][j].w + W[m*4+1]*xn[1][j].w + W[m*4+2]*xn[2][j].w + W[m*4+3]*xn[3][j].w;
            __stcs(&out[base + (size_t)m * 256 + (size_t)j * 128], o);
        }
    }
}

extern "C" void kernel_launch(void* const* d_in, const int* in_sizes, int n_in,
                              void* d_out, int out_size) {
    const float* x    = (const float*)d_in[0];
    const float* pre  = (const float*)d_in[1];
    const float* post = (const float*)d_in[2];
    const float* res  = (const float*)d_in[3];
    float* out = (float*)d_out;

    // 16384 rows x 128 threads/row = 2.097M threads, 8192 blocks of 256
    const unsigned total_threads = 16384u * 128u;
    hc_fused_kernel<<<total_threads / 256u, 256u>>>(
        (const float4*)x, (float4*)out, pre, post, res);
}